// round 2
// baseline (speedup 1.0000x reference)
#include <cuda_runtime.h>
#include <math.h>

// ---------------- problem constants ----------------
#define BB 32
#define CC 2048
#define HH 48
#define WW 24
#define PP 3
#define ICC 128     // IC
#define C4 512
#define PHH 16
#define HD 8
#define WD 12
#define NN 96       // HD*WD
#define BN3 3072    // BB*NN

// ---------------- scratch (device globals; no allocs allowed) ----------------
__device__ float d_xd  [(size_t)PP*CC*BN3];   // (P,C,B*N)
__device__ float d_t   [(size_t)PP*CC*BN3];   // (P,C,B*N)
__device__ float d_ao  [(size_t)PP*CC*BN3];   // (P,C,B*N)
__device__ float d_qk  [(size_t)PP*256*BN3];  // (P,256,B*N): rows 0..127 q, 128..255 k
__device__ float d_wqk [(size_t)PP*256*CC];   // fused q/k weights
__device__ float d_qkb [(size_t)PP*256];      // fused q/k biases
__device__ float d_attnT[(size_t)BB*PP*NN*NN];// (B*P, j, i) = attn[i][j]
__device__ float d_gap [(size_t)PP*CC*BB];    // (P,C,B)
__device__ float d_h1  [(size_t)PP*C4*BB];    // (P,512,B)
__device__ float d_cw  [(size_t)PP*CC*BB];    // (P,C,B)
__device__ float d_mw  [BB*PP];

// ---------------- packed fp32x2 helpers (sm_103a: 2x FFMA throughput) ----------------
__device__ __forceinline__ unsigned long long pk2(float lo, float hi){
    unsigned long long r;
    asm("mov.b64 %0, {%1, %2};" : "=l"(r) : "f"(lo), "f"(hi));
    return r;
}
__device__ __forceinline__ unsigned long long ffma2(unsigned long long a, unsigned long long b, unsigned long long c){
    unsigned long long d;
    asm("fma.rn.f32x2 %0, %1, %2, %3;" : "=l"(d) : "l"(a), "l"(b), "l"(c));
    return d;
}
__device__ __forceinline__ float2 upk2(unsigned long long v){
    float2 f;
    asm("mov.b64 {%0, %1}, %2;" : "=f"(f.x), "=f"(f.y) : "l"(v));
    return f;
}

// ---------------- generic batched SGEMM: C = A(MxK) * B(KxN) + bias, row-major ----------------
// EPI: 0 = bias only, 1 = bias+relu, 2 = bias+sigmoid
template<int BM,int BN,int BK,int TM,int TN,int EPI>
__global__ void __launch_bounds__((BM/TM)*(BN/TN))
sgemm_k(const float* __restrict__ A, const float* __restrict__ B,
        float* __restrict__ C, const float* __restrict__ bias,
        int M, int N, int K, long long sA, long long sB, long long sC, int sBias)
{
    constexpr int THREADS = (BM/TM)*(BN/TN);
    constexpr int TN2 = TN/2;
    __shared__ float As[BK][BM];
    __shared__ float Bs[BK][BN];
    const int p = blockIdx.z;
    A += (long long)p * sA;
    B += (long long)p * sB;
    C += (long long)p * sC;
    const float* bp = bias + (long long)p * sBias;
    const int bm = blockIdx.y * BM, bn = blockIdx.x * BN;
    const int tid = threadIdx.x;
    const int tcol = tid % (BN/TN);
    const int trow = tid / (BN/TN);

    unsigned long long acc[TM][TN2];
    #pragma unroll
    for (int i=0;i<TM;i++)
        #pragma unroll
        for (int j=0;j<TN2;j++) acc[i][j] = 0ull;

    for (int k0 = 0; k0 < K; k0 += BK) {
        #pragma unroll
        for (int i = tid; i < BM*BK; i += THREADS) {
            int r = i / BK, c = i % BK;
            As[c][r] = A[(long long)(bm + r) * K + k0 + c];
        }
        #pragma unroll
        for (int i = tid; i < BK*BN; i += THREADS) {
            int r = i / BN, c = i % BN;
            Bs[r][c] = B[(long long)(k0 + r) * N + bn + c];
        }
        __syncthreads();
        #pragma unroll
        for (int kk = 0; kk < BK; kk++) {
            unsigned long long av[TM];
            unsigned long long bv[TN2];
            #pragma unroll
            for (int i=0;i<TM;i++){ float a = As[kk][trow*TM + i]; av[i] = pk2(a, a); }
            const float2* brow = reinterpret_cast<const float2*>(&Bs[kk][tcol*TN]);
            #pragma unroll
            for (int j=0;j<TN2;j++){ float2 b2 = brow[j]; bv[j] = pk2(b2.x, b2.y); }
            #pragma unroll
            for (int i=0;i<TM;i++)
                #pragma unroll
                for (int j=0;j<TN2;j++)
                    acc[i][j] = ffma2(av[i], bv[j], acc[i][j]);
        }
        __syncthreads();
    }

    #pragma unroll
    for (int i=0;i<TM;i++) {
        int m = bm + trow*TM + i;
        float bvl = bp[m];
        #pragma unroll
        for (int j=0;j<TN2;j++) {
            float2 v = upk2(acc[i][j]);
            float v0 = v.x + bvl, v1 = v.y + bvl;
            if (EPI == 1) { v0 = v0 > 0.f ? v0 : 0.f; v1 = v1 > 0.f ? v1 : 0.f; }
            if (EPI == 2) { v0 = 1.f/(1.f+expf(-v0)); v1 = 1.f/(1.f+expf(-v1)); }
            int n = bn + tcol*TN + 2*j;
            C[(long long)m * N + n]     = v0;
            C[(long long)m * N + n + 1] = v1;
        }
    }
}

// ---------------- prep: fused q/k weights ----------------
__global__ void wqk_kernel(const float* __restrict__ pa_q_w, const float* __restrict__ pa_dw_q_w,
                           const float* __restrict__ pa_k_w, const float* __restrict__ pa_dw_k_w,
                           float* __restrict__ wqk)
{
    int idx = blockIdx.x * 256 + threadIdx.x;
    if (idx >= PP*256*CC) return;
    int c = idx & (CC-1);
    int r = idx >> 11;
    int i = r % 256, p = r / 256;
    float v;
    if (i < ICC) v = pa_q_w[((long long)p*ICC + i)*CC + c] * pa_dw_q_w[p*CC + c];
    else         v = pa_k_w[((long long)p*ICC + (i-ICC))*CC + c] * pa_dw_k_w[p*CC + c];
    wqk[idx] = v;
}

// ---------------- prep: fused q/k biases ----------------
__global__ void __launch_bounds__(256)
qkb_kernel(const float* __restrict__ pa_q_w, const float* __restrict__ pa_dw_q_b, const float* __restrict__ pa_q_b,
           const float* __restrict__ pa_k_w, const float* __restrict__ pa_dw_k_b, const float* __restrict__ pa_k_b,
           float* __restrict__ qkb)
{
    int w = blockIdx.x * 8 + threadIdx.x / 32;
    int lane = threadIdx.x & 31;
    if (w >= PP*256) return;
    int i = w % 256, p = w / 256;
    const float* Wp; const float* db; float base;
    if (i < ICC) { Wp = pa_q_w + ((long long)p*ICC + i)*CC; db = pa_dw_q_b + p*CC; base = pa_q_b[p*ICC + i]; }
    else         { Wp = pa_k_w + ((long long)p*ICC + (i-ICC))*CC; db = pa_dw_k_b + p*CC; base = pa_k_b[p*ICC + (i-ICC)]; }
    float s = 0.f;
    for (int c = lane; c < CC; c += 32) s += Wp[c] * db[c];
    #pragma unroll
    for (int o = 16; o > 0; o >>= 1) s += __shfl_xor_sync(0xffffffffu, s, o);
    if (lane == 0) qkb[w] = base + s;
}

// ---------------- prep: modality gate ----------------
__global__ void mw_kernel(const int* __restrict__ modality, const float* __restrict__ gw1,
                          const float* __restrict__ gb1, const float* __restrict__ gw2,
                          const float* __restrict__ gb2, float* __restrict__ mw)
{
    int t = threadIdx.x;
    if (t >= BB*PP) return;
    int b = t / PP, p = t % PP;
    float mf = (float)modality[b];
    float s = gb2[p];
    #pragma unroll
    for (int j = 0; j < 12; j++) {
        float g = mf * gw1[j] + gb1[j];
        g = g > 0.f ? g : 0.f;
        s += g * gw2[p*12 + j];
    }
    mw[t] = 1.f / (1.f + expf(-s));
}

// ---------------- 2x2 avg pool into (P,C,B*N) ----------------
__global__ void __launch_bounds__(256)
pool_kernel(const float* __restrict__ x, float* __restrict__ xd)
{
    long long idx = (long long)blockIdx.x * 256 + threadIdx.x;
    if (idx >= (long long)PP*CC*BN3) return;
    int n = (int)(idx % NN); long long r = idx / NN;
    int b = (int)(r % BB); r /= BB;
    int c = (int)(r % CC); int p = (int)(r / CC);
    int hd = n / WD, wd = n % WD;
    long long base = ((long long)(b*CC + c)*HH + p*PHH + 2*hd)*WW + 2*wd;
    float2 r0 = *reinterpret_cast<const float2*>(x + base);
    float2 r1 = *reinterpret_cast<const float2*>(x + base + WW);
    xd[idx] = (r0.x + r0.y + r1.x + r1.y) * 0.25f;
}

// ---------------- energy + softmax -> attnT ----------------
__global__ void __launch_bounds__(256)
attn_kernel(const float* __restrict__ qk, float* __restrict__ attnT)
{
    extern __shared__ float sm[];
    float* qs = sm;              // 128*96
    float* ks = sm + ICC*NN;     // 128*96
    const int bp = blockIdx.x;   // b*P + p
    const int b = bp / PP, p = bp % PP;
    const int tid = threadIdx.x;
    const float* qbase = qk + (long long)p*256*BN3 + b*NN;
    for (int i = tid; i < ICC*NN; i += 256) {
        int r = i / NN, n = i % NN;
        qs[i] = qbase[(long long)r*BN3 + n];
        ks[i] = qbase[(long long)(ICC + r)*BN3 + n];
    }
    __syncthreads();
    const int tn0 = (tid % 16) * 6, tm0 = (tid / 16) * 6;
    float acc[6][6] = {};
    for (int i = 0; i < ICC; i++) {
        float qf[6], kf[6];
        #pragma unroll
        for (int a=0;a<6;a++){ qf[a]=qs[i*NN+tn0+a]; kf[a]=ks[i*NN+tm0+a]; }
        #pragma unroll
        for (int a=0;a<6;a++)
            #pragma unroll
            for (int m=0;m<6;m++) acc[a][m] = fmaf(qf[a], kf[m], acc[a][m]);
    }
    __syncthreads();
    float* es = sm;              // reuse as 96*96 energy
    #pragma unroll
    for (int a=0;a<6;a++)
        #pragma unroll
        for (int m=0;m<6;m++) es[(tn0+a)*NN + tm0+m] = acc[a][m];
    __syncthreads();
    const int warp = tid / 32, lane = tid & 31;
    float* dst = attnT + (long long)bp * NN * NN;
    for (int n = warp; n < NN; n += 8) {
        float v0 = es[n*NN + lane], v1 = es[n*NN + 32 + lane], v2 = es[n*NN + 64 + lane];
        float mx = fmaxf(v0, fmaxf(v1, v2));
        #pragma unroll
        for (int o=16;o>0;o>>=1) mx = fmaxf(mx, __shfl_xor_sync(0xffffffffu, mx, o));
        v0 = expf(v0 - mx); v1 = expf(v1 - mx); v2 = expf(v2 - mx);
        float s = v0 + v1 + v2;
        #pragma unroll
        for (int o=16;o>0;o>>=1) s += __shfl_xor_sync(0xffffffffu, s, o);
        float inv = 1.f / s;
        dst[(lane)*NN + n]      = v0 * inv;   // attnT[j][i] = attn[i=n][j=m]
        dst[(lane+32)*NN + n]   = v1 * inv;
        dst[(lane+64)*NN + n]   = v2 * inv;
    }
}

// ---------------- t = xd @ attnT (block-diagonal per (b,p)) ----------------
__global__ void __launch_bounds__(256)
t_kernel(const float* __restrict__ xd, const float* __restrict__ attnT, float* __restrict__ tOut)
{
    extern __shared__ float sm[];
    float* aT = sm;                 // 96*96
    float* xs = sm + NN*NN;         // 64*97 (padded)
    const int c0 = blockIdx.x * 64;
    const int b = blockIdx.y, p = blockIdx.z;
    const int tid = threadIdx.x;
    const float* asrc = attnT + (long long)(b*PP + p)*NN*NN;
    for (int i = tid; i < NN*NN; i += 256) aT[i] = asrc[i];
    const float* xbase = xd + (long long)(p*CC + c0)*BN3 + b*NN;
    for (int i = tid; i < 64*NN; i += 256) {
        int r = i / NN, n = i % NN;
        xs[r*97 + n] = xbase[(long long)r*BN3 + n];
    }
    __syncthreads();
    const int tx = tid % 16, ty = tid / 16;
    const int i0 = tx * 6, cc0 = ty * 4;
    unsigned long long acc[4][3];
    #pragma unroll
    for (int a=0;a<4;a++)
        #pragma unroll
        for (int u=0;u<3;u++) acc[a][u] = 0ull;
    for (int j = 0; j < NN; j++) {
        unsigned long long av[4], bv[3];
        #pragma unroll
        for (int a=0;a<4;a++){ float v = xs[(cc0+a)*97 + j]; av[a] = pk2(v, v); }
        const float2* br = reinterpret_cast<const float2*>(&aT[j*NN + i0]);
        #pragma unroll
        for (int u=0;u<3;u++){ float2 t2 = br[u]; bv[u] = pk2(t2.x, t2.y); }
        #pragma unroll
        for (int a=0;a<4;a++)
            #pragma unroll
            for (int u=0;u<3;u++) acc[a][u] = ffma2(av[a], bv[u], acc[a][u]);
    }
    float* dst = tOut + (long long)(p*CC + c0)*BN3 + b*NN;
    #pragma unroll
    for (int a=0;a<4;a++)
        #pragma unroll
        for (int u=0;u<3;u++) {
            float2 v = upk2(acc[a][u]);
            dst[(long long)(cc0+a)*BN3 + i0 + 2*u]     = v.x;
            dst[(long long)(cc0+a)*BN3 + i0 + 2*u + 1] = v.y;
        }
}

// ---------------- gap (uses mean(up) == mean(ao row)) ----------------
__global__ void __launch_bounds__(256)
gap_kernel(const float* __restrict__ ao, const float* __restrict__ x,
           const float* __restrict__ pa_gamma, float* __restrict__ gapT)
{
    int w = blockIdx.x * 8 + threadIdx.x / 32;
    int lane = threadIdx.x & 31;
    int bp = w >> 11, c = w & (CC-1);
    int b = bp / PP, p = bp % PP;
    const float* aob = ao + (long long)(p*CC + c)*BN3 + b*NN;
    float sa = aob[lane] + aob[lane+32] + aob[lane+64];
    const float* xb = x + ((long long)(b*CC + c)*HH + p*PHH)*WW;
    float sx = 0.f;
    #pragma unroll
    for (int u = 0; u < 12; u++) sx += xb[lane + 32*u];
    #pragma unroll
    for (int o = 16; o > 0; o >>= 1) {
        sa += __shfl_xor_sync(0xffffffffu, sa, o);
        sx += __shfl_xor_sync(0xffffffffu, sx, o);
    }
    if (lane == 0)
        gapT[(long long)(p*CC + c)*BB + b] = pa_gamma[p]*(sa*(1.f/96.f)) + sx*(1.f/384.f);
}

// ---------------- fused final: upsample + residual + SE + modality gate ----------------
__global__ void __launch_bounds__(384)
final_kernel(const float* __restrict__ x, const float* __restrict__ ao,
             const float* __restrict__ cw, const float* __restrict__ mw,
             const float* __restrict__ pa_gamma, const float* __restrict__ ca_gamma,
             float* __restrict__ out)
{
    __shared__ float as_[NN];
    const int c = blockIdx.x;
    const int bp = blockIdx.y;
    const int b = bp / PP, p = bp % PP;
    const int tid = threadIdx.x;
    if (tid < NN) as_[tid] = ao[(long long)(p*CC + c)*BN3 + b*NN + tid];
    __syncthreads();
    const int y = tid / WW, xw = tid % WW;
    int ky = y >> 1, kx = xw >> 1;
    int y0, y1, x0, x1; float wy0, wy1, wx0, wx1;
    if ((y & 1) == 0) { y0 = ky > 0 ? ky-1 : 0; y1 = ky; wy0 = 0.25f; wy1 = 0.75f; }
    else              { y0 = ky; y1 = ky < HD-1 ? ky+1 : HD-1; wy0 = 0.75f; wy1 = 0.25f; }
    if ((xw & 1) == 0){ x0 = kx > 0 ? kx-1 : 0; x1 = kx; wx0 = 0.25f; wx1 = 0.75f; }
    else              { x0 = kx; x1 = kx < WD-1 ? kx+1 : WD-1; wx0 = 0.75f; wx1 = 0.25f; }
    float up = wy0*(wx0*as_[y0*WD + x0] + wx1*as_[y0*WD + x1])
             + wy1*(wx0*as_[y1*WD + x0] + wx1*as_[y1*WD + x1]);
    long long xi = ((long long)(b*CC + c)*HH + p*PHH + y)*WW + xw;
    float xpv = x[xi];
    float pa  = pa_gamma[p]*up + xpv;
    float cwv = cw[(long long)(p*CC + c)*BB + b];
    float ca  = ca_gamma[p]*(pa*cwv) + pa;
    float w   = mw[b*PP + p];
    out[xi] = xpv*(1.f - w) + ca*w;
}

// ---------------- launcher ----------------
extern "C" void kernel_launch(void* const* d_in, const int* in_sizes, int n_in,
                              void* d_out, int out_size)
{
    const float* x          = (const float*)d_in[0];
    const float* pa_dw_q_w  = (const float*)d_in[1];
    const float* pa_dw_q_b  = (const float*)d_in[2];
    const float* pa_q_w     = (const float*)d_in[3];
    const float* pa_q_b     = (const float*)d_in[4];
    const float* pa_dw_k_w  = (const float*)d_in[5];
    const float* pa_dw_k_b  = (const float*)d_in[6];
    const float* pa_k_w     = (const float*)d_in[7];
    const float* pa_k_b     = (const float*)d_in[8];
    const float* pa_v_w     = (const float*)d_in[9];
    const float* pa_v_b     = (const float*)d_in[10];
    const float* pa_gamma   = (const float*)d_in[11];
    const float* ca_fc1_w   = (const float*)d_in[12];
    const float* ca_fc1_b   = (const float*)d_in[13];
    const float* ca_fc2_w   = (const float*)d_in[14];
    const float* ca_fc2_b   = (const float*)d_in[15];
    const float* ca_gamma   = (const float*)d_in[16];
    const float* gate_w1    = (const float*)d_in[17];
    const float* gate_b1    = (const float*)d_in[18];
    const float* gate_w2    = (const float*)d_in[19];
    const float* gate_b2    = (const float*)d_in[20];
    const int*   modality   = (const int*)d_in[21];
    float* out = (float*)d_out;

    float *g_xd, *g_t, *g_ao, *g_qk, *g_wqk, *g_qkb, *g_attnT, *g_gap, *g_h1, *g_cw, *g_mw;
    cudaGetSymbolAddress((void**)&g_xd, d_xd);
    cudaGetSymbolAddress((void**)&g_t, d_t);
    cudaGetSymbolAddress((void**)&g_ao, d_ao);
    cudaGetSymbolAddress((void**)&g_qk, d_qk);
    cudaGetSymbolAddress((void**)&g_wqk, d_wqk);
    cudaGetSymbolAddress((void**)&g_qkb, d_qkb);
    cudaGetSymbolAddress((void**)&g_attnT, d_attnT);
    cudaGetSymbolAddress((void**)&g_gap, d_gap);
    cudaGetSymbolAddress((void**)&g_h1, d_h1);
    cudaGetSymbolAddress((void**)&g_cw, d_cw);
    cudaGetSymbolAddress((void**)&g_mw, d_mw);

    cudaFuncSetAttribute(attn_kernel, cudaFuncAttributeMaxDynamicSharedMemorySize, 2*ICC*NN*4);
    cudaFuncSetAttribute(t_kernel,    cudaFuncAttributeMaxDynamicSharedMemorySize, (NN*NN + 64*97)*4);

    // prep
    wqk_kernel<<<(PP*256*CC)/256, 256>>>(pa_q_w, pa_dw_q_w, pa_k_w, pa_dw_k_w, g_wqk);
    qkb_kernel<<<(PP*256)/8, 256>>>(pa_q_w, pa_dw_q_b, pa_q_b, pa_k_w, pa_dw_k_b, pa_k_b, g_qkb);
    mw_kernel<<<1, 128>>>(modality, gate_w1, gate_b1, gate_w2, gate_b2, g_mw);

    // pool
    pool_kernel<<<(int)(((long long)PP*CC*BN3)/256), 256>>>(x, g_xd);

    // qk = Wqk' @ xd + b'   (M=256, N=3072, K=2048, batched over p)
    sgemm_k<128,128,8,8,8,0><<<dim3(BN3/128, 256/128, PP), 256>>>(
        g_wqk, g_xd, g_qk, g_qkb, 256, BN3, CC,
        (long long)256*CC, (long long)CC*BN3, (long long)256*BN3, 256);

    // attention
    attn_kernel<<<BB*PP, 256, 2*ICC*NN*4>>>(g_qk, g_attnT);

    // t = xd @ attnT
    t_kernel<<<dim3(CC/64, BB, PP), 256, (NN*NN + 64*97)*4>>>(g_xd, g_attnT, g_t);

    // ao = Wv @ t + vb   (M=2048, N=3072, K=2048, batched over p)
    sgemm_k<128,128,8,8,8,0><<<dim3(BN3/128, CC/128, PP), 256>>>(
        pa_v_w, g_t, g_ao, pa_v_b, CC, BN3, CC,
        (long long)CC*CC, (long long)CC*BN3, (long long)CC*BN3, CC);

    // gap
    gap_kernel<<<(BB*PP*CC)/8, 256>>>(g_ao, x, pa_gamma, g_gap);

    // SE block: h1 = relu(fc1 @ gap + b1); cw = sigmoid(fc2 @ h1 + b2)
    sgemm_k<64,32,16,4,2,1><<<dim3(1, C4/64, PP), 256>>>(
        ca_fc1_w, g_gap, g_h1, ca_fc1_b, C4, BB, CC,
        (long long)C4*CC, (long long)CC*BB, (long long)C4*BB, C4);
    sgemm_k<64,32,16,4,2,2><<<dim3(1, CC/64, PP), 256>>>(
        ca_fc2_w, g_h1, g_cw, ca_fc2_b, CC, BB, C4,
        (long long)CC*C4, (long long)C4*BB, (long long)CC*BB, CC);

    // fused upsample + residual + SE + gate
    final_kernel<<<dim3(CC, BB*PP), 384>>>(x, g_ao, g_cw, g_mw, pa_gamma, ca_gamma, out);
}

// round 5
// speedup vs baseline: 2.2708x; 2.2708x over previous
#include <cuda_runtime.h>
#include <cuda_bf16.h>
#include <math.h>
#include <stdint.h>

// ---------------- problem constants ----------------
#define BB 32
#define CC 2048
#define HH 48
#define WW 24
#define PP 3
#define ICC 128     // IC
#define C4 512
#define PHH 16
#define HD 8
#define WD 12
#define NN 96       // HD*WD
#define BN3 3072    // BB*NN

// ---------------- scratch (device globals; no allocs allowed) ----------------
__device__ float d_xd  [(size_t)PP*CC*BN3];   // (P,C,B*N) f32
__device__ float d_xdT [(size_t)PP*BN3*CC];   // (P,B*N,C) tf32-rounded
__device__ float d_tT  [(size_t)PP*BN3*CC];   // (P,B*N,C) tf32-rounded (t transposed)
__device__ float d_ao  [(size_t)PP*CC*BN3];   // (P,C,B*N)
__device__ float d_qk  [(size_t)PP*256*BN3];  // (P,256,B*N): rows 0..127 q, 128..255 k
__device__ float d_wqk [(size_t)PP*256*CC];   // fused q/k weights, tf32-rounded
__device__ float d_wv  [(size_t)PP*CC*CC];    // Wv tf32-rounded
__device__ float d_qkb [(size_t)PP*256];
__device__ float d_attnT[(size_t)BB*PP*NN*NN];
__device__ float d_gap [(size_t)PP*CC*BB];
__device__ float d_h1  [(size_t)PP*C4*BB];
__device__ float d_cw  [(size_t)PP*CC*BB];
__device__ float d_mw  [BB*PP];

// ---------------- packed fp32x2 helpers ----------------
__device__ __forceinline__ unsigned long long pk2(float lo, float hi){
    unsigned long long r;
    asm("mov.b64 %0, {%1, %2};" : "=l"(r) : "f"(lo), "f"(hi));
    return r;
}
__device__ __forceinline__ unsigned long long ffma2(unsigned long long a, unsigned long long b, unsigned long long c){
    unsigned long long d;
    asm("fma.rn.f32x2 %0, %1, %2, %3;" : "=l"(d) : "l"(a), "l"(b), "l"(c));
    return d;
}
__device__ __forceinline__ float2 upk2(unsigned long long v){
    float2 f;
    asm("mov.b64 {%0, %1}, %2;" : "=f"(f.x), "=f"(f.y) : "l"(v));
    return f;
}

// ---------------- tf32 helpers ----------------
__device__ __forceinline__ float to_tf32(float x){
    uint32_t r;
    asm("cvt.rna.tf32.f32 %0, %1;" : "=r"(r) : "f"(x));
    return __uint_as_float(r);
}
__device__ __forceinline__ void mma_tf32(float* c, const float* a, const float* b){
    asm volatile("mma.sync.aligned.m16n8k8.row.col.f32.tf32.tf32.f32 "
        "{%0,%1,%2,%3}, {%4,%5,%6,%7}, {%8,%9}, {%0,%1,%2,%3};"
        : "+f"(c[0]), "+f"(c[1]), "+f"(c[2]), "+f"(c[3])
        : "r"(__float_as_uint(a[0])), "r"(__float_as_uint(a[1])),
          "r"(__float_as_uint(a[2])), "r"(__float_as_uint(a[3])),
          "r"(__float_as_uint(b[0])), "r"(__float_as_uint(b[1])));
}
__device__ __forceinline__ uint32_t smem_u32(const void* p){
    uint32_t a;
    asm("{ .reg .u64 t; cvta.to.shared.u64 t, %1; cvt.u32.u64 %0, t; }" : "=r"(a) : "l"(p));
    return a;
}
__device__ __forceinline__ void cp16(uint32_t dst, const void* src){
    asm volatile("cp.async.cg.shared.global [%0], [%1], 16;" :: "r"(dst), "l"(src));
}
#define CP_COMMIT() asm volatile("cp.async.commit_group;" ::: "memory")
#define CP_WAIT(n)  asm volatile("cp.async.wait_group %0;" :: "n"(n) : "memory")

// ============================================================================
// tf32 mma.sync GEMM: C[M,N] = sum_k A[m,k]*B[n,k] + bias[m]
// A: [M][K] row-major (tf32-rounded f32); B: [N][K] row-major (tf32-rounded)
// CTA tile 128x128, BK=32, 128 threads (4 warps, 64x64 warp tiles), 2-stage cp.async
// ============================================================================
#define MG_STRIDE 36
#define MG_SMEM (2*2*128*MG_STRIDE*4)   // 2 stages * (A+B) * 128 rows * 36 floats

__global__ void __launch_bounds__(128, 2)
mma_gemm(const float* __restrict__ A, const float* __restrict__ B,
         float* __restrict__ C, const float* __restrict__ bias,
         int N, int K, long long sA, long long sB, long long sC, int sBias)
{
    extern __shared__ float smf[];
    const uint32_t su = smem_u32(smf);
    // layout: As[stage][128][36], Bs[stage][128][36]
    const int tid = threadIdx.x;
    const int p = blockIdx.z;
    const int bm = blockIdx.y * 128, bn = blockIdx.x * 128;
    const float* Ap = A + (size_t)p * sA + (size_t)bm * K;
    const float* Bp = B + (size_t)p * sB + (size_t)bn * K;

    const int lane = tid & 31, warp = tid >> 5;
    const int wm = (warp & 1) * 64, wn = (warp >> 1) * 64;
    const int g = lane >> 2, t = lane & 3;

    float acc[4][8][4];
    #pragma unroll
    for (int mt=0; mt<4; mt++)
        #pragma unroll
        for (int nt=0; nt<8; nt++)
            #pragma unroll
            for (int r=0; r<4; r++) acc[mt][nt][r] = 0.f;

    const int row0 = tid >> 3, seg0 = (tid & 7) * 4;

    auto load = [&](int k0, int s){
        uint32_t aBase = su + ((s*128 + row0)*MG_STRIDE + seg0) * 4;
        uint32_t bBase = aBase + 2*128*MG_STRIDE*4;
        #pragma unroll
        for (int i = 0; i < 8; i++) {
            cp16(aBase + i*16*MG_STRIDE*4, Ap + (size_t)(row0 + i*16)*K + k0 + seg0);
            cp16(bBase + i*16*MG_STRIDE*4, Bp + (size_t)(row0 + i*16)*K + k0 + seg0);
        }
        CP_COMMIT();
    };

    const float* AsBase = smf;
    const float* BsBase = smf + 2*128*MG_STRIDE;

    const int nC = K / 32;
    load(0, 0);
    for (int i = 0; i < nC; i++) {
        const int s = i & 1;
        if (i + 1 < nC) { load((i+1)*32, (i+1)&1); CP_WAIT(1); }
        else            { CP_WAIT(0); }
        __syncthreads();
        const float* As = AsBase + s*128*MG_STRIDE;
        const float* Bs = BsBase + s*128*MG_STRIDE;
        #pragma unroll
        for (int k = 0; k < 4; k++) {
            const int kk = k * 8;
            float a[4][4], b[8][2];
            #pragma unroll
            for (int mt = 0; mt < 4; mt++) {
                const int r = wm + mt*16;
                a[mt][0] = As[(r+g  )*MG_STRIDE + kk + t];
                a[mt][1] = As[(r+g+8)*MG_STRIDE + kk + t];
                a[mt][2] = As[(r+g  )*MG_STRIDE + kk + t + 4];
                a[mt][3] = As[(r+g+8)*MG_STRIDE + kk + t + 4];
            }
            #pragma unroll
            for (int nt = 0; nt < 8; nt++) {
                const int r = wn + nt*8;
                b[nt][0] = Bs[(r+g)*MG_STRIDE + kk + t];
                b[nt][1] = Bs[(r+g)*MG_STRIDE + kk + t + 4];
            }
            #pragma unroll
            for (int mt = 0; mt < 4; mt++)
                #pragma unroll
                for (int nt = 0; nt < 8; nt++)
                    mma_tf32(acc[mt][nt], a[mt], b[nt]);
        }
        __syncthreads();
    }

    // epilogue: c0=(g,2t) c1=(g,2t+1) c2=(g+8,2t) c3=(g+8,2t+1)
    const float* bp = bias + (size_t)p * sBias + bm;
    float* Cp = C + (size_t)p * sC + (size_t)bm * N + bn;
    #pragma unroll
    for (int mt = 0; mt < 4; mt++) {
        const int r0 = wm + mt*16 + g;
        const float bv0 = bp[r0], bv1 = bp[r0 + 8];
        #pragma unroll
        for (int nt = 0; nt < 8; nt++) {
            const int col = wn + nt*8 + 2*t;
            float2 v0 = make_float2(acc[mt][nt][0] + bv0, acc[mt][nt][1] + bv0);
            float2 v1 = make_float2(acc[mt][nt][2] + bv1, acc[mt][nt][3] + bv1);
            *reinterpret_cast<float2*>(Cp + (size_t)r0*N + col)       = v0;
            *reinterpret_cast<float2*>(Cp + (size_t)(r0+8)*N + col)   = v1;
        }
    }
}

// ---------------- round weights to tf32 ----------------
__global__ void __launch_bounds__(256)
round_kernel(const float* __restrict__ in, float* __restrict__ out, long long n)
{
    long long i = (long long)blockIdx.x * 256 + threadIdx.x;
    if (i < n) out[i] = to_tf32(in[i]);
}

// ---------------- xd (P,C,BN3) -> xdT (P,BN3,C) tf32-rounded ----------------
__global__ void __launch_bounds__(256)
xdT_kernel(const float* __restrict__ xd, float* __restrict__ out)
{
    __shared__ float tile[32][33];
    const int p = blockIdx.z;
    const int n0 = blockIdx.x * 32, c0 = blockIdx.y * 32;
    const int tx = threadIdx.x & 31, ty = threadIdx.x >> 5;
    #pragma unroll
    for (int r = 0; r < 32; r += 8)
        tile[ty + r][tx] = xd[((size_t)p * CC + c0 + ty + r) * BN3 + n0 + tx];
    __syncthreads();
    #pragma unroll
    for (int r = 0; r < 32; r += 8)
        out[((size_t)p * BN3 + n0 + ty + r) * CC + c0 + tx] = to_tf32(tile[tx][ty + r]);
}

// ---------------- generic small SGEMM (SE block only) ----------------
template<int BM,int BN,int BK,int TM,int TN,int EPI>
__global__ void __launch_bounds__((BM/TM)*(BN/TN))
sgemm_k(const float* __restrict__ A, const float* __restrict__ B,
        float* __restrict__ C, const float* __restrict__ bias,
        int M, int N, int K, long long sA, long long sB, long long sC, int sBias)
{
    constexpr int THREADS = (BM/TM)*(BN/TN);
    constexpr int TN2 = TN/2;
    __shared__ float As[BK][BM];
    __shared__ float Bs[BK][BN];
    const int p = blockIdx.z;
    A += (long long)p * sA;
    B += (long long)p * sB;
    C += (long long)p * sC;
    const float* bp = bias + (long long)p * sBias;
    const int bm = blockIdx.y * BM, bn = blockIdx.x * BN;
    const int tid = threadIdx.x;
    const int tcol = tid % (BN/TN);
    const int trow = tid / (BN/TN);

    unsigned long long acc[TM][TN2];
    #pragma unroll
    for (int i=0;i<TM;i++)
        #pragma unroll
        for (int j=0;j<TN2;j++) acc[i][j] = 0ull;

    for (int k0 = 0; k0 < K; k0 += BK) {
        #pragma unroll
        for (int i = tid; i < BM*BK; i += THREADS) {
            int r = i / BK, c = i % BK;
            As[c][r] = A[(long long)(bm + r) * K + k0 + c];
        }
        #pragma unroll
        for (int i = tid; i < BK*BN; i += THREADS) {
            int r = i / BN, c = i % BN;
            Bs[r][c] = B[(long long)(k0 + r) * N + bn + c];
        }
        __syncthreads();
        #pragma unroll
        for (int kk = 0; kk < BK; kk++) {
            unsigned long long av[TM], bv[TN2];
            #pragma unroll
            for (int i=0;i<TM;i++){ float a = As[kk][trow*TM + i]; av[i] = pk2(a, a); }
            const float2* brow = reinterpret_cast<const float2*>(&Bs[kk][tcol*TN]);
            #pragma unroll
            for (int j=0;j<TN2;j++){ float2 b2 = brow[j]; bv[j] = pk2(b2.x, b2.y); }
            #pragma unroll
            for (int i=0;i<TM;i++)
                #pragma unroll
                for (int j=0;j<TN2;j++)
                    acc[i][j] = ffma2(av[i], bv[j], acc[i][j]);
        }
        __syncthreads();
    }

    #pragma unroll
    for (int i=0;i<TM;i++) {
        int m = bm + trow*TM + i;
        float bvl = bp[m];
        #pragma unroll
        for (int j=0;j<TN2;j++) {
            float2 v = upk2(acc[i][j]);
            float v0 = v.x + bvl, v1 = v.y + bvl;
            if (EPI == 1) { v0 = v0 > 0.f ? v0 : 0.f; v1 = v1 > 0.f ? v1 : 0.f; }
            if (EPI == 2) { v0 = 1.f/(1.f+expf(-v0)); v1 = 1.f/(1.f+expf(-v1)); }
            int n = bn + tcol*TN + 2*j;
            C[(long long)m * N + n]     = v0;
            C[(long long)m * N + n + 1] = v1;
        }
    }
}

// ---------------- prep: fused q/k weights (tf32-rounded) ----------------
__global__ void wqk_kernel(const float* __restrict__ pa_q_w, const float* __restrict__ pa_dw_q_w,
                           const float* __restrict__ pa_k_w, const float* __restrict__ pa_dw_k_w,
                           float* __restrict__ wqk)
{
    int idx = blockIdx.x * 256 + threadIdx.x;
    if (idx >= PP*256*CC) return;
    int c = idx & (CC-1);
    int r = idx >> 11;
    int i = r % 256, p = r / 256;
    float v;
    if (i < ICC) v = pa_q_w[((long long)p*ICC + i)*CC + c] * pa_dw_q_w[p*CC + c];
    else         v = pa_k_w[((long long)p*ICC + (i-ICC))*CC + c] * pa_dw_k_w[p*CC + c];
    wqk[idx] = to_tf32(v);
}

// ---------------- prep: fused q/k biases ----------------
__global__ void __launch_bounds__(256)
qkb_kernel(const float* __restrict__ pa_q_w, const float* __restrict__ pa_dw_q_b, const float* __restrict__ pa_q_b,
           const float* __restrict__ pa_k_w, const float* __restrict__ pa_dw_k_b, const float* __restrict__ pa_k_b,
           float* __restrict__ qkb)
{
    int w = blockIdx.x * 8 + threadIdx.x / 32;
    int lane = threadIdx.x & 31;
    if (w >= PP*256) return;
    int i = w % 256, p = w / 256;
    const float* Wp; const float* db; float base;
    if (i < ICC) { Wp = pa_q_w + ((long long)p*ICC + i)*CC; db = pa_dw_q_b + p*CC; base = pa_q_b[p*ICC + i]; }
    else         { Wp = pa_k_w + ((long long)p*ICC + (i-ICC))*CC; db = pa_dw_k_b + p*CC; base = pa_k_b[p*ICC + (i-ICC)]; }
    float s = 0.f;
    for (int c = lane; c < CC; c += 32) s += Wp[c] * db[c];
    #pragma unroll
    for (int o = 16; o > 0; o >>= 1) s += __shfl_xor_sync(0xffffffffu, s, o);
    if (lane == 0) qkb[w] = base + s;
}

// ---------------- prep: modality gate ----------------
__global__ void mw_kernel(const int* __restrict__ modality, const float* __restrict__ gw1,
                          const float* __restrict__ gb1, const float* __restrict__ gw2,
                          const float* __restrict__ gb2, float* __restrict__ mw)
{
    int t = threadIdx.x;
    if (t >= BB*PP) return;
    int b = t / PP, p = t % PP;
    float mf = (float)modality[b];
    float s = gb2[p];
    #pragma unroll
    for (int j = 0; j < 12; j++) {
        float g = mf * gw1[j] + gb1[j];
        g = g > 0.f ? g : 0.f;
        s += g * gw2[p*12 + j];
    }
    mw[t] = 1.f / (1.f + expf(-s));
}

// ---------------- 2x2 avg pool into (P,C,B*N) ----------------
__global__ void __launch_bounds__(256)
pool_kernel(const float* __restrict__ x, float* __restrict__ xd)
{
    long long idx = (long long)blockIdx.x * 256 + threadIdx.x;
    if (idx >= (long long)PP*CC*BN3) return;
    int n = (int)(idx % NN); long long r = idx / NN;
    int b = (int)(r % BB); r /= BB;
    int c = (int)(r % CC); int p = (int)(r / CC);
    int hd = n / WD, wd = n % WD;
    long long base = ((long long)(b*CC + c)*HH + p*PHH + 2*hd)*WW + 2*wd;
    float2 r0 = *reinterpret_cast<const float2*>(x + base);
    float2 r1 = *reinterpret_cast<const float2*>(x + base + WW);
    xd[idx] = (r0.x + r0.y + r1.x + r1.y) * 0.25f;
}

// ---------------- energy + softmax -> attnT ----------------
__global__ void __launch_bounds__(256)
attn_kernel(const float* __restrict__ qk, float* __restrict__ attnT)
{
    extern __shared__ float sm[];
    float* qs = sm;              // 128*96
    float* ks = sm + ICC*NN;     // 128*96
    const int bp = blockIdx.x;   // b*P + p
    const int b = bp / PP, p = bp % PP;
    const int tid = threadIdx.x;
    const float* qbase = qk + (long long)p*256*BN3 + b*NN;
    for (int i = tid; i < ICC*NN; i += 256) {
        int r = i / NN, n = i % NN;
        qs[i] = qbase[(long long)r*BN3 + n];
        ks[i] = qbase[(long long)(ICC + r)*BN3 + n];
    }
    __syncthreads();
    const int tn0 = (tid % 16) * 6, tm0 = (tid / 16) * 6;
    float acc[6][6] = {};
    for (int i = 0; i < ICC; i++) {
        float qf[6], kf[6];
        #pragma unroll
        for (int a=0;a<6;a++){ qf[a]=qs[i*NN+tn0+a]; kf[a]=ks[i*NN+tm0+a]; }
        #pragma unroll
        for (int a=0;a<6;a++)
            #pragma unroll
            for (int m=0;m<6;m++) acc[a][m] = fmaf(qf[a], kf[m], acc[a][m]);
    }
    __syncthreads();
    float* es = sm;              // reuse as 96*96 energy
    #pragma unroll
    for (int a=0;a<6;a++)
        #pragma unroll
        for (int m=0;m<6;m++) es[(tn0+a)*NN + tm0+m] = acc[a][m];
    __syncthreads();
    const int warp = tid / 32, lane = tid & 31;
    float* dst = attnT + (long long)bp * NN * NN;
    for (int n = warp; n < NN; n += 8) {
        float v0 = es[n*NN + lane], v1 = es[n*NN + 32 + lane], v2 = es[n*NN + 64 + lane];
        float mx = fmaxf(v0, fmaxf(v1, v2));
        #pragma unroll
        for (int o=16;o>0;o>>=1) mx = fmaxf(mx, __shfl_xor_sync(0xffffffffu, mx, o));
        v0 = expf(v0 - mx); v1 = expf(v1 - mx); v2 = expf(v2 - mx);
        float s = v0 + v1 + v2;
        #pragma unroll
        for (int o=16;o>0;o>>=1) s += __shfl_xor_sync(0xffffffffu, s, o);
        float inv = 1.f / s;
        dst[(lane)*NN + n]      = v0 * inv;
        dst[(lane+32)*NN + n]   = v1 * inv;
        dst[(lane+64)*NN + n]   = v2 * inv;
    }
}

// ---------------- t = xd @ attnT; writes transposed tf32-rounded (P,BN3,C) ----------------
#define TK_SMEM ((NN*NN + 64*97 + NN*65)*4)
__global__ void __launch_bounds__(256)
t_kernel(const float* __restrict__ xd, const float* __restrict__ attnT, float* __restrict__ tT)
{
    extern __shared__ float sm[];
    float* aT = sm;                 // 96*96
    float* xs = sm + NN*NN;         // 64*97
    float* ot = sm + NN*NN + 64*97; // 96*65
    const int c0 = blockIdx.x * 64;
    const int b = blockIdx.y, p = blockIdx.z;
    const int tid = threadIdx.x;
    const float* asrc = attnT + (long long)(b*PP + p)*NN*NN;
    for (int i = tid; i < NN*NN; i += 256) aT[i] = asrc[i];
    const float* xbase = xd + (long long)(p*CC + c0)*BN3 + b*NN;
    for (int i = tid; i < 64*NN; i += 256) {
        int r = i / NN, n = i % NN;
        xs[r*97 + n] = xbase[(long long)r*BN3 + n];
    }
    __syncthreads();
    const int tx = tid % 16, ty = tid / 16;
    const int i0 = tx * 6, cc0 = ty * 4;
    unsigned long long acc[4][3];
    #pragma unroll
    for (int a=0;a<4;a++)
        #pragma unroll
        for (int u=0;u<3;u++) acc[a][u] = 0ull;
    for (int j = 0; j < NN; j++) {
        unsigned long long av[4], bv[3];
        #pragma unroll
        for (int a=0;a<4;a++){ float v = xs[(cc0+a)*97 + j]; av[a] = pk2(v, v); }
        const float2* br = reinterpret_cast<const float2*>(&aT[j*NN + i0]);
        #pragma unroll
        for (int u=0;u<3;u++){ float2 t2 = br[u]; bv[u] = pk2(t2.x, t2.y); }
        #pragma unroll
        for (int a=0;a<4;a++)
            #pragma unroll
            for (int u=0;u<3;u++) acc[a][u] = ffma2(av[a], bv[u], acc[a][u]);
    }
    // stage transposed tf32-rounded result: ot[i (n-dim)][c]
    #pragma unroll
    for (int a=0;a<4;a++)
        #pragma unroll
        for (int u=0;u<3;u++) {
            float2 v = upk2(acc[a][u]);
            ot[(i0 + 2*u    )*65 + cc0 + a] = to_tf32(v.x);
            ot[(i0 + 2*u + 1)*65 + cc0 + a] = to_tf32(v.y);
        }
    __syncthreads();
    float* dst = tT + ((size_t)p*BN3 + b*NN) * CC + c0;
    for (int idx = tid; idx < NN*64; idx += 256) {
        int i = idx >> 6, c = idx & 63;
        dst[(size_t)i * CC + c] = ot[i*65 + c];
    }
}

// ---------------- gap ----------------
__global__ void __launch_bounds__(256)
gap_kernel(const float* __restrict__ ao, const float* __restrict__ x,
           const float* __restrict__ pa_gamma, float* __restrict__ gapT)
{
    int w = blockIdx.x * 8 + threadIdx.x / 32;
    int lane = threadIdx.x & 31;
    int bp = w >> 11, c = w & (CC-1);
    int b = bp / PP, p = bp % PP;
    const float* aob = ao + (long long)(p*CC + c)*BN3 + b*NN;
    float sa = aob[lane] + aob[lane+32] + aob[lane+64];
    const float* xb = x + ((long long)(b*CC + c)*HH + p*PHH)*WW;
    float sx = 0.f;
    #pragma unroll
    for (int u = 0; u < 12; u++) sx += xb[lane + 32*u];
    #pragma unroll
    for (int o = 16; o > 0; o >>= 1) {
        sa += __shfl_xor_sync(0xffffffffu, sa, o);
        sx += __shfl_xor_sync(0xffffffffu, sx, o);
    }
    if (lane == 0)
        gapT[(long long)(p*CC + c)*BB + b] = pa_gamma[p]*(sa*(1.f/96.f)) + sx*(1.f/384.f);
}

// ---------------- fused final ----------------
__global__ void __launch_bounds__(384)
final_kernel(const float* __restrict__ x, const float* __restrict__ ao,
             const float* __restrict__ cw, const float* __restrict__ mw,
             const float* __restrict__ pa_gamma, const float* __restrict__ ca_gamma,
             float* __restrict__ out)
{
    __shared__ float as_[NN];
    const int c = blockIdx.x;
    const int bp = blockIdx.y;
    const int b = bp / PP, p = bp % PP;
    const int tid = threadIdx.x;
    if (tid < NN) as_[tid] = ao[(long long)(p*CC + c)*BN3 + b*NN + tid];
    __syncthreads();
    const int y = tid / WW, xw = tid % WW;
    int ky = y >> 1, kx = xw >> 1;
    int y0, y1, x0, x1; float wy0, wy1, wx0, wx1;
    if ((y & 1) == 0) { y0 = ky > 0 ? ky-1 : 0; y1 = ky; wy0 = 0.25f; wy1 = 0.75f; }
    else              { y0 = ky; y1 = ky < HD-1 ? ky+1 : HD-1; wy0 = 0.75f; wy1 = 0.25f; }
    if ((xw & 1) == 0){ x0 = kx > 0 ? kx-1 : 0; x1 = kx; wx0 = 0.25f; wx1 = 0.75f; }
    else              { x0 = kx; x1 = kx < WD-1 ? kx+1 : WD-1; wx0 = 0.75f; wx1 = 0.25f; }
    float up = wy0*(wx0*as_[y0*WD + x0] + wx1*as_[y0*WD + x1])
             + wy1*(wx0*as_[y1*WD + x0] + wx1*as_[y1*WD + x1]);
    long long xi = ((long long)(b*CC + c)*HH + p*PHH + y)*WW + xw;
    float xpv = x[xi];
    float pa  = pa_gamma[p]*up + xpv;
    float cwv = cw[(long long)(p*CC + c)*BB + b];
    float ca  = ca_gamma[p]*(pa*cwv) + pa;
    float w   = mw[b*PP + p];
    out[xi] = xpv*(1.f - w) + ca*w;
}

// ---------------- launcher ----------------
extern "C" void kernel_launch(void* const* d_in, const int* in_sizes, int n_in,
                              void* d_out, int out_size)
{
    const float* x          = (const float*)d_in[0];
    const float* pa_dw_q_w  = (const float*)d_in[1];
    const float* pa_dw_q_b  = (const float*)d_in[2];
    const float* pa_q_w     = (const float*)d_in[3];
    const float* pa_q_b     = (const float*)d_in[4];
    const float* pa_dw_k_w  = (const float*)d_in[5];
    const float* pa_dw_k_b  = (const float*)d_in[6];
    const float* pa_k_w     = (const float*)d_in[7];
    const float* pa_k_b     = (const float*)d_in[8];
    const float* pa_v_w     = (const float*)d_in[9];
    const float* pa_v_b     = (const float*)d_in[10];
    const float* pa_gamma   = (const float*)d_in[11];
    const float* ca_fc1_w   = (const float*)d_in[12];
    const float* ca_fc1_b   = (const float*)d_in[13];
    const float* ca_fc2_w   = (const float*)d_in[14];
    const float* ca_fc2_b   = (const float*)d_in[15];
    const float* ca_gamma   = (const float*)d_in[16];
    const float* gate_w1    = (const float*)d_in[17];
    const float* gate_b1    = (const float*)d_in[18];
    const float* gate_w2    = (const float*)d_in[19];
    const float* gate_b2    = (const float*)d_in[20];
    const int*   modality   = (const int*)d_in[21];
    float* out = (float*)d_out;

    float *g_xd, *g_xdT, *g_tT, *g_ao, *g_qk, *g_wqk, *g_wv, *g_qkb, *g_attnT, *g_gap, *g_h1, *g_cw, *g_mw;
    cudaGetSymbolAddress((void**)&g_xd, d_xd);
    cudaGetSymbolAddress((void**)&g_xdT, d_xdT);
    cudaGetSymbolAddress((void**)&g_tT, d_tT);
    cudaGetSymbolAddress((void**)&g_ao, d_ao);
    cudaGetSymbolAddress((void**)&g_qk, d_qk);
    cudaGetSymbolAddress((void**)&g_wqk, d_wqk);
    cudaGetSymbolAddress((void**)&g_wv, d_wv);
    cudaGetSymbolAddress((void**)&g_qkb, d_qkb);
    cudaGetSymbolAddress((void**)&g_attnT, d_attnT);
    cudaGetSymbolAddress((void**)&g_gap, d_gap);
    cudaGetSymbolAddress((void**)&g_h1, d_h1);
    cudaGetSymbolAddress((void**)&g_cw, d_cw);
    cudaGetSymbolAddress((void**)&g_mw, d_mw);

    cudaFuncSetAttribute(attn_kernel, cudaFuncAttributeMaxDynamicSharedMemorySize, 2*ICC*NN*4);
    cudaFuncSetAttribute(t_kernel,    cudaFuncAttributeMaxDynamicSharedMemorySize, TK_SMEM);
    cudaFuncSetAttribute(mma_gemm,    cudaFuncAttributeMaxDynamicSharedMemorySize, MG_SMEM);

    // prep
    wqk_kernel<<<(PP*256*CC)/256, 256>>>(pa_q_w, pa_dw_q_w, pa_k_w, pa_dw_k_w, g_wqk);
    qkb_kernel<<<(PP*256)/8, 256>>>(pa_q_w, pa_dw_q_b, pa_q_b, pa_k_w, pa_dw_k_b, pa_k_b, g_qkb);
    mw_kernel<<<1, 128>>>(modality, gate_w1, gate_b1, gate_w2, gate_b2, g_mw);
    round_kernel<<<(int)(((long long)PP*CC*CC + 255)/256), 256>>>(pa_v_w, g_wv, (long long)PP*CC*CC);

    // pool + transpose/round
    pool_kernel<<<(int)(((long long)PP*CC*BN3)/256), 256>>>(x, g_xd);
    xdT_kernel<<<dim3(BN3/32, CC/32, PP), 256>>>(g_xd, g_xdT);

    // qk = Wqk' @ xd + b'   (tf32 tensor cores, M=256, N=3072, K=2048)
    mma_gemm<<<dim3(BN3/128, 256/128, PP), 128, MG_SMEM>>>(
        g_wqk, g_xdT, g_qk, g_qkb, BN3, CC,
        (long long)256*CC, (long long)BN3*CC, (long long)256*BN3, 256);

    // attention
    attn_kernel<<<BB*PP, 256, 2*ICC*NN*4>>>(g_qk, g_attnT);

    // t = xd @ attnT -> transposed tf32-rounded
    t_kernel<<<dim3(CC/64, BB, PP), 256, TK_SMEM>>>(g_xd, g_attnT, g_tT);

    // ao = Wv @ t + vb   (tf32 tensor cores, M=2048, N=3072, K=2048)
    mma_gemm<<<dim3(BN3/128, CC/128, PP), 128, MG_SMEM>>>(
        g_wv, g_tT, g_ao, pa_v_b, BN3, CC,
        (long long)CC*CC, (long long)BN3*CC, (long long)CC*BN3, CC);

    // gap
    gap_kernel<<<(BB*PP*CC)/8, 256>>>(g_ao, x, pa_gamma, g_gap);

    // SE block
    sgemm_k<64,32,16,4,2,1><<<dim3(1, C4/64, PP), 256>>>(
        ca_fc1_w, g_gap, g_h1, ca_fc1_b, C4, BB, CC,
        (long long)C4*CC, (long long)CC*BB, (long long)C4*BB, C4);
    sgemm_k<64,32,16,4,2,2><<<dim3(1, CC/64, PP), 256>>>(
        ca_fc2_w, g_h1, g_cw, ca_fc2_b, CC, BB, C4,
        (long long)CC*C4, (long long)C4*BB, (long long)CC*BB, CC);

    // fused upsample + residual + SE + gate
    final_kernel<<<dim3(CC, BB*PP), 384>>>(x, g_ao, g_cw, g_mw, pa_gamma, ca_gamma, out);
}